// round 2
// baseline (speedup 1.0000x reference)
#include <cuda_runtime.h>
#include <math.h>

#define B_ 8
#define T_ 2048
#define C_ 2048
#define H_ 32
#define HS_ 64
#define M_ (B_*T_)   // 16384

// ---------------- scratch (__device__ globals: allocation-free) ----------------
__device__ float g_tm [(size_t)M_*160];
__device__ float g_xr [(size_t)M_*C_];
__device__ float g_xk [(size_t)M_*C_];
__device__ float g_xv [(size_t)M_*C_];
__device__ float g_xw [(size_t)M_*C_];
__device__ float g_xv2[(size_t)M_*C_];
__device__ float g_r  [(size_t)M_*C_];
__device__ float g_k  [(size_t)M_*C_];
__device__ float g_v  [(size_t)M_*C_];
__device__ float g_v2 [(size_t)M_*C_];
__device__ float g_d  [(size_t)M_*C_];
__device__ float g_lw [(size_t)M_*64];
__device__ float g_lv2[(size_t)M_*64];
__device__ float g_yw [(size_t)M_*C_];
__device__ float g_yln[(size_t)M_*C_];

// ---------------- skinny GEMM + tanh:  out[M,NS] = tanh(A[M,C] @ W[C,NS]) ----------------
// FUSE=true: A is x; compute xxx = x + (xprev - x)*maa_x on the fly (token shift).
template<int NS, bool FUSE>
__global__ void __launch_bounds__(256) skinny_tanh_gemm(
    const float* __restrict__ A, const float* __restrict__ W,
    float* __restrict__ out,
    const float* __restrict__ shift, const float* __restrict__ maax)
{
    __shared__ float As[32*68];       // [k][m] transposed, padded
    __shared__ float Ws[32*NS];
    const int tid = threadIdx.x;
    const int m0  = blockIdx.x * 64;
    const int row = tid >> 2;         // 0..63
    const int cg  = tid & 3;

    float acc[NS/4];
#pragma unroll
    for (int i = 0; i < NS/4; i++) acc[i] = 0.f;

    for (int k0 = 0; k0 < C_; k0 += 32) {
        // A tile: 64 rows x 32 cols
#pragma unroll
        for (int e = 0; e < 2; e++) {
            int q  = tid + 256*e;
            int r  = q >> 3;
            int c4 = (q & 7) * 4;
            int m  = m0 + r;
            float4 val;
            if (FUSE) {
                float4 xv = *(const float4*)(A + (size_t)m*C_ + k0 + c4);
                int t = m & (T_-1);
                int b = m >> 11;
                float4 xp = (t > 0) ? *(const float4*)(A + (size_t)(m-1)*C_ + k0 + c4)
                                    : *(const float4*)(shift + (size_t)b*C_ + k0 + c4);
                float4 mx = *(const float4*)(maax + k0 + c4);
                val.x = xv.x + (xp.x - xv.x)*mx.x;
                val.y = xv.y + (xp.y - xv.y)*mx.y;
                val.z = xv.z + (xp.z - xv.z)*mx.z;
                val.w = xv.w + (xp.w - xv.w)*mx.w;
            } else {
                val = *(const float4*)(A + (size_t)m*C_ + k0 + c4);
            }
            As[(c4+0)*68 + r] = val.x;
            As[(c4+1)*68 + r] = val.y;
            As[(c4+2)*68 + r] = val.z;
            As[(c4+3)*68 + r] = val.w;
        }
        // W tile: rows k0..k0+31 are contiguous (32*NS floats)
        {
            const float4* src = (const float4*)(W + (size_t)k0*NS);
            for (int q = tid; q < 32*NS/4; q += 256)
                ((float4*)Ws)[q] = src[q];
        }
        __syncthreads();
#pragma unroll 8
        for (int k = 0; k < 32; k++) {
            float a = As[k*68 + row];
            const float* wrow = Ws + k*NS + cg*(NS/4);
#pragma unroll
            for (int j = 0; j < NS/16; j++) {
                float4 w4 = *(const float4*)(wrow + j*4);
                acc[j*4+0] = fmaf(a, w4.x, acc[j*4+0]);
                acc[j*4+1] = fmaf(a, w4.y, acc[j*4+1]);
                acc[j*4+2] = fmaf(a, w4.z, acc[j*4+2]);
                acc[j*4+3] = fmaf(a, w4.w, acc[j*4+3]);
            }
        }
        __syncthreads();
    }
    float* orow = out + (size_t)(m0+row)*NS + cg*(NS/4);
#pragma unroll
    for (int i = 0; i < NS/4; i++) orow[i] = tanhf(acc[i]);
}

// ---------------- 5-way mix apply (one f per launch) ----------------
// out = x + dxprev * (maa_f + tm[:,f,:] @ w2[f])
__global__ void __launch_bounds__(256) mix_apply_f(
    const float* __restrict__ x, const float* __restrict__ shift,
    const float* __restrict__ tm, const float* __restrict__ w2,
    const float* __restrict__ maa, float* __restrict__ out, int f)
{
    __shared__ float tmf[32*32];
    __shared__ float w2f[32*64];
    int tid = threadIdx.x;
    int m0 = blockIdx.y * 32;
    int c0 = blockIdx.x * 64;
    {
        int r = tid >> 3, c4 = (tid & 7) * 4;
        *(float4*)&tmf[r*32 + c4] =
            *(const float4*)(tm + (size_t)(m0+r)*160 + f*32 + c4);
    }
#pragma unroll
    for (int e = 0; e < 2; e++) {
        int q = tid + 256*e;
        int d = q >> 4, c4 = (q & 15) * 4;
        *(float4*)&w2f[d*64 + c4] =
            *(const float4*)(w2 + (size_t)(f*32+d)*C_ + c0 + c4);
    }
    __syncthreads();
#pragma unroll
    for (int e = 0; e < 2; e++) {
        int p = tid + 256*e;
        int r  = p >> 4;
        int c4 = (p & 15) * 4;
        int m = m0 + r;
        int c = c0 + c4;
        float4 acc = make_float4(0.f,0.f,0.f,0.f);
#pragma unroll
        for (int d = 0; d < 32; d++) {
            float tv = tmf[r*32 + d];
            float4 w4 = *(const float4*)&w2f[d*64 + c4];
            acc.x = fmaf(tv, w4.x, acc.x);
            acc.y = fmaf(tv, w4.y, acc.y);
            acc.z = fmaf(tv, w4.z, acc.z);
            acc.w = fmaf(tv, w4.w, acc.w);
        }
        float4 xv = *(const float4*)(x + (size_t)m*C_ + c);
        int t = m & (T_-1), b = m >> 11;
        float4 xp = (t > 0) ? *(const float4*)(x + (size_t)(m-1)*C_ + c)
                            : *(const float4*)(shift + (size_t)b*C_ + c);
        float4 ma = *(const float4*)(maa + c);
        float4 o;
        o.x = xv.x + (xp.x - xv.x)*(ma.x + acc.x);
        o.y = xv.y + (xp.y - xv.y)*(ma.y + acc.y);
        o.z = xv.z + (xp.z - xv.z)*(ma.z + acc.z);
        o.w = xv.w + (xp.w - xv.w)*(ma.w + acc.w);
        *(float4*)(out + (size_t)m*C_ + c) = o;
    }
}

// ---------------- big GEMM: C[M,N] = A[M,K] @ B[K,N], fp32, 128x128x16 ----------------
__global__ void __launch_bounds__(256,2) gemm_f32(
    const float* __restrict__ A, const float* __restrict__ Bm,
    float* __restrict__ Cm, int M, int N, int K)
{
    __shared__ float As[2][16*132];
    __shared__ float Bs[2][16*128];
    int tid = threadIdx.x;
    int bx = blockIdx.x, by = blockIdx.y;
    const float* Ab = A  + (size_t)by*128*K;
    const float* Bb = Bm + (size_t)bx*128;
    int ty = tid >> 4, tx = tid & 15;

    float acc[8][8];
#pragma unroll
    for (int i = 0; i < 8; i++)
#pragma unroll
        for (int j = 0; j < 8; j++) acc[i][j] = 0.f;

    int ar[2], akc[2], bkr[2], bc4[2];
#pragma unroll
    for (int e = 0; e < 2; e++) {
        int q = tid + 256*e;
        ar[e]  = q >> 2;        akc[e] = (q & 3) * 4;
        bkr[e] = q >> 5;        bc4[e] = (q & 31) * 4;
    }
    float4 pa[2], pb[2];
#pragma unroll
    for (int e = 0; e < 2; e++) {
        pa[e] = *(const float4*)(Ab + (size_t)ar[e]*K + akc[e]);
        pb[e] = *(const float4*)(Bb + (size_t)bkr[e]*N + bc4[e]);
    }
#pragma unroll
    for (int e = 0; e < 2; e++) {
        As[0][(akc[e]+0)*132 + ar[e]] = pa[e].x;
        As[0][(akc[e]+1)*132 + ar[e]] = pa[e].y;
        As[0][(akc[e]+2)*132 + ar[e]] = pa[e].z;
        As[0][(akc[e]+3)*132 + ar[e]] = pa[e].w;
        *(float4*)&Bs[0][bkr[e]*128 + bc4[e]] = pb[e];
    }
    __syncthreads();

    int nt = K >> 4;
    for (int tile = 0; tile < nt; tile++) {
        int cur = tile & 1;
        if (tile + 1 < nt) {
            int k0 = (tile + 1) << 4;
#pragma unroll
            for (int e = 0; e < 2; e++) {
                pa[e] = *(const float4*)(Ab + (size_t)ar[e]*K + k0 + akc[e]);
                pb[e] = *(const float4*)(Bb + (size_t)(k0 + bkr[e])*N + bc4[e]);
            }
        }
#pragma unroll
        for (int kk = 0; kk < 16; kk++) {
            float4 a0 = *(const float4*)&As[cur][kk*132 + ty*8];
            float4 a1 = *(const float4*)&As[cur][kk*132 + ty*8 + 4];
            float4 b0 = *(const float4*)&Bs[cur][kk*128 + tx*8];
            float4 b1 = *(const float4*)&Bs[cur][kk*128 + tx*8 + 4];
            float av[8] = {a0.x,a0.y,a0.z,a0.w,a1.x,a1.y,a1.z,a1.w};
            float bv[8] = {b0.x,b0.y,b0.z,b0.w,b1.x,b1.y,b1.z,b1.w};
#pragma unroll
            for (int i = 0; i < 8; i++)
#pragma unroll
                for (int j = 0; j < 8; j++)
                    acc[i][j] = fmaf(av[i], bv[j], acc[i][j]);
        }
        if (tile + 1 < nt) {
            int nxt = cur ^ 1;
#pragma unroll
            for (int e = 0; e < 2; e++) {
                As[nxt][(akc[e]+0)*132 + ar[e]] = pa[e].x;
                As[nxt][(akc[e]+1)*132 + ar[e]] = pa[e].y;
                As[nxt][(akc[e]+2)*132 + ar[e]] = pa[e].z;
                As[nxt][(akc[e]+3)*132 + ar[e]] = pa[e].w;
                *(float4*)&Bs[nxt][bkr[e]*128 + bc4[e]] = pb[e];
            }
            __syncthreads();
        }
    }
    size_t crow = (size_t)(by*128 + ty*8);
    int    ccol = bx*128 + tx*8;
#pragma unroll
    for (int i = 0; i < 8; i++) {
        float4 o0 = make_float4(acc[i][0],acc[i][1],acc[i][2],acc[i][3]);
        float4 o1 = make_float4(acc[i][4],acc[i][5],acc[i][6],acc[i][7]);
        *(float4*)(Cm + (crow+i)*N + ccol)     = o0;
        *(float4*)(Cm + (crow+i)*N + ccol + 4) = o1;
    }
}

// ---------------- small-K GEMM (K=64) with fused epilogues ----------------
// MODE 0: w = td[c] + A@W; d = exp(-exp(w)); store d; k *= (1-d)
// MODE 1: out1 += A@W
template<int MODE>
__global__ void __launch_bounds__(256) smallk_gemm(
    const float* __restrict__ A, const float* __restrict__ W,
    const float* __restrict__ td, float* __restrict__ out1,
    float* __restrict__ karr)
{
    __shared__ float As[32*64];
    __shared__ float Ws[64*128];
    int tid = threadIdx.x;
    int m0 = blockIdx.y * 32, c0 = blockIdx.x * 128;
    {
        const float4* src = (const float4*)(A + (size_t)m0*64);
#pragma unroll
        for (int q = tid; q < 512; q += 256) ((float4*)As)[q] = src[q];
    }
#pragma unroll
    for (int e = 0; e < 8; e++) {
        int q = tid + 256*e;
        int kr = q >> 5, c4 = (q & 31) * 4;
        *(float4*)&Ws[kr*128 + c4] = *(const float4*)(W + (size_t)kr*C_ + c0 + c4);
    }
    __syncthreads();
    int ty = tid >> 4, tx = tid & 15;
    int r0 = ty * 2;
    float acc[2][8];
#pragma unroll
    for (int i = 0; i < 2; i++)
#pragma unroll
        for (int j = 0; j < 8; j++) acc[i][j] = 0.f;
#pragma unroll
    for (int k = 0; k < 64; k++) {
        float a0 = As[r0*64 + k];
        float a1 = As[(r0+1)*64 + k];
        float4 b0 = *(const float4*)&Ws[k*128 + tx*8];
        float4 b1 = *(const float4*)&Ws[k*128 + tx*8 + 4];
        float bv[8] = {b0.x,b0.y,b0.z,b0.w,b1.x,b1.y,b1.z,b1.w};
#pragma unroll
        for (int j = 0; j < 8; j++) {
            acc[0][j] = fmaf(a0, bv[j], acc[0][j]);
            acc[1][j] = fmaf(a1, bv[j], acc[1][j]);
        }
    }
#pragma unroll
    for (int rr = 0; rr < 2; rr++) {
        int m = m0 + r0 + rr;
        size_t base = (size_t)m*C_ + c0 + tx*8;
        if (MODE == 0) {
#pragma unroll
            for (int j = 0; j < 8; j++) {
                float w = td[c0 + tx*8 + j] + acc[rr][j];
                float dd = expf(-expf(w));
                out1[base + j] = dd;
                karr[base + j] *= (1.0f - dd);
            }
        } else {
#pragma unroll
            for (int j = 0; j < 8; j++) out1[base + j] += acc[rr][j];
        }
    }
}

// ---------------- WKV linear-recurrent scan, one block per (b,h) ----------------
__global__ void __launch_bounds__(64) wkv_scan(
    const float* __restrict__ rp, const float* __restrict__ kp,
    const float* __restrict__ vp, const float* __restrict__ dp,
    const float* __restrict__ S0, float* __restrict__ yp,
    float* __restrict__ Sout)
{
    int bh = blockIdx.x;
    int j = threadIdx.x;
    int b = bh >> 5, h = bh & (H_-1);
    float S[64];
    const float* s0 = S0 + (size_t)bh*HS_*HS_ + j;
#pragma unroll
    for (int i = 0; i < 64; i++) S[i] = s0[(size_t)i*64];
    __shared__ float4 skd[64];
    size_t idx = (size_t)b*T_*C_ + (size_t)h*64 + j;
    float rr = rp[idx], kk = kp[idx], dd = dp[idx], vv = vp[idx];
    for (int t = 0; t < T_; t++) {
        float rn = 0.f, kn = 0.f, dn = 0.f, vn = 0.f;
        if (t + 1 < T_) {
            size_t nx = idx + C_;
            rn = rp[nx]; kn = kp[nx]; dn = dp[nx]; vn = vp[nx];
        }
        skd[j] = make_float4(rr, kk, dd, 0.f);
        __syncthreads();
        float acc = 0.f;
#pragma unroll
        for (int i = 0; i < 64; i++) {
            float4 q = skd[i];
            acc  = fmaf(q.x, S[i], acc);       // y uses pre-update state (u==0)
            S[i] = fmaf(q.z, S[i], q.y * vv);  // S = d*S + k v^T
        }
        yp[idx] = acc;
        __syncthreads();
        idx += C_;
        rr = rn; kk = kn; dd = dn; vv = vn;
    }
    float* so = Sout + (size_t)bh*HS_*HS_ + j;
#pragma unroll
    for (int i = 0; i < 64; i++) so[(size_t)i*64] = S[i];
}

// ---------------- fused add + LayerNorm ----------------
__global__ void __launch_bounds__(256) ln_add(
    const float* __restrict__ a, const float* __restrict__ b,
    const float* __restrict__ lw, const float* __restrict__ lb,
    float* __restrict__ out)
{
    int m = blockIdx.x;
    int tid = threadIdx.x;
    const float* ar = a + (size_t)m*C_;
    const float* br = b + (size_t)m*C_;
    float vals[8];
    float s = 0.f, s2 = 0.f;
#pragma unroll
    for (int i = 0; i < 8; i++) {
        int c = tid + 256*i;
        float u = ar[c] + br[c];
        vals[i] = u; s += u; s2 = fmaf(u, u, s2);
    }
#pragma unroll
    for (int o = 16; o > 0; o >>= 1) {
        s  += __shfl_xor_sync(0xffffffffu, s,  o);
        s2 += __shfl_xor_sync(0xffffffffu, s2, o);
    }
    __shared__ float sa[8], sb[8];
    if ((tid & 31) == 0) { sa[tid>>5] = s; sb[tid>>5] = s2; }
    __syncthreads();
    s = 0.f; s2 = 0.f;
#pragma unroll
    for (int i = 0; i < 8; i++) { s += sa[i]; s2 += sb[i]; }
    float mu  = s * (1.0f/C_);
    float var = s2 * (1.0f/C_) - mu*mu;
    float inv = rsqrtf(var + 1e-5f);
    float* orow = out + (size_t)m*C_;
#pragma unroll
    for (int i = 0; i < 8; i++) {
        int c = tid + 256*i;
        orow[c] = (vals[i] - mu)*inv*lw[c] + lb[c];
    }
}

__global__ void copy_xlast(const float* __restrict__ x, float* __restrict__ o)
{
    int i = blockIdx.x*256 + threadIdx.x;   // B_*C_ threads total
    int b = i >> 11, c = i & (C_-1);
    o[i] = x[((size_t)b*T_ + (T_-1))*C_ + c];
}

// ---------------- launcher ----------------
extern "C" void kernel_launch(void* const* d_in, const int* in_sizes, int n_in,
                              void* d_out, int out_size)
{
    (void)in_sizes; (void)n_in;
    const float* x     = (const float*)d_in[0];
    const float* shift = (const float*)d_in[1];
    const float* wkv0  = (const float*)d_in[2];
    const float* maax  = (const float*)d_in[3];
    const float* maar  = (const float*)d_in[4];
    const float* maak  = (const float*)d_in[5];
    const float* maav  = (const float*)d_in[6];
    const float* maaw  = (const float*)d_in[7];
    const float* maav2 = (const float*)d_in[8];
    const float* w1    = (const float*)d_in[9];
    const float* w2    = (const float*)d_in[10];
    const float* tdec  = (const float*)d_in[11];
    const float* dw1   = (const float*)d_in[12];
    const float* dw2   = (const float*)d_in[13];
    const float* vw1   = (const float*)d_in[14];
    const float* vw2   = (const float*)d_in[15];
    const float* Wr    = (const float*)d_in[17];
    const float* Wk    = (const float*)d_in[18];
    const float* Wv    = (const float*)d_in[19];
    const float* Wo    = (const float*)d_in[20];
    const float* lnw   = (const float*)d_in[21];
    const float* lnb   = (const float*)d_in[22];
    float* out = (float*)d_out;

    float *tm,*xr,*xk,*xv,*xw,*xv2,*rb,*kb,*vb,*v2b,*db,*lwv,*lv2,*yw,*yln;
    cudaGetSymbolAddress((void**)&tm,  g_tm);
    cudaGetSymbolAddress((void**)&xr,  g_xr);
    cudaGetSymbolAddress((void**)&xk,  g_xk);
    cudaGetSymbolAddress((void**)&xv,  g_xv);
    cudaGetSymbolAddress((void**)&xw,  g_xw);
    cudaGetSymbolAddress((void**)&xv2, g_xv2);
    cudaGetSymbolAddress((void**)&rb,  g_r);
    cudaGetSymbolAddress((void**)&kb,  g_k);
    cudaGetSymbolAddress((void**)&vb,  g_v);
    cudaGetSymbolAddress((void**)&v2b, g_v2);
    cudaGetSymbolAddress((void**)&db,  g_d);
    cudaGetSymbolAddress((void**)&lwv, g_lw);
    cudaGetSymbolAddress((void**)&lv2, g_lv2);
    cudaGetSymbolAddress((void**)&yw,  g_yw);
    cudaGetSymbolAddress((void**)&yln, g_yln);

    // 1) LoRA-5 projection with fused token-shift mixing: tm = tanh(xxx @ w1)
    skinny_tanh_gemm<160, true><<<M_/64, 256>>>(x, w1, tm, shift, maax);

    // 2) 5-way mix: xr/xk/xv/xw/xv2
    {
        dim3 g(C_/64, M_/32);
        mix_apply_f<<<g,256>>>(x, shift, tm, w2, maar,  xr,  0);
        mix_apply_f<<<g,256>>>(x, shift, tm, w2, maak,  xk,  1);
        mix_apply_f<<<g,256>>>(x, shift, tm, w2, maav,  xv,  2);
        mix_apply_f<<<g,256>>>(x, shift, tm, w2, maaw,  xw,  3);
        mix_apply_f<<<g,256>>>(x, shift, tm, w2, maav2, xv2, 4);
    }

    // 3) big projections
    dim3 gg(C_/128, M_/128);
    gemm_f32<<<gg,256>>>(xr,  Wr, rb,  M_, C_, C_);
    gemm_f32<<<gg,256>>>(xk,  Wk, kb,  M_, C_, C_);
    gemm_f32<<<gg,256>>>(xv,  Wv, vb,  M_, C_, C_);
    gemm_f32<<<gg,256>>>(xv2, Wv, v2b, M_, C_, C_);

    // 4) decay / value2 LoRAs
    skinny_tanh_gemm<64, false><<<M_/64, 256>>>(xw,  dw1, lwv, nullptr, nullptr);
    skinny_tanh_gemm<64, false><<<M_/64, 256>>>(xv2, vw1, lv2, nullptr, nullptr);
    {
        dim3 gs(C_/128, M_/32);
        smallk_gemm<0><<<gs,256>>>(lwv, dw2, tdec, db,  kb);       // d, k*(1-d)
        smallk_gemm<1><<<gs,256>>>(lv2, vw2, nullptr, v2b, nullptr); // v2 += lora
    }

    // 5) WKV scan (+ S_final), 6) add v2 + LayerNorm, 7) output projection
    const size_t OFFS = (size_t)M_*C_;
    const size_t OFFX = OFFS + (size_t)B_*H_*HS_*HS_;
    bool full = (size_t)out_size >= OFFX + (size_t)B_*C_;
    float* Sout = full ? (out + OFFS) : tm;   // tm is dead by now; safe scratch
    wkv_scan<<<B_*H_, 64>>>(rb, kb, vb, db, wkv0, yw, Sout);
    ln_add<<<M_, 256>>>(yw, v2b, lnw, lnb, yln);
    gemm_f32<<<gg,256>>>(yln, Wo, out, M_, C_, C_);
    if (full) copy_xlast<<<(B_*C_)/256, 256>>>(x, out + OFFX);
}

// round 4
// speedup vs baseline: 1.7174x; 1.7174x over previous
#include <cuda_runtime.h>
#include <cuda_bf16.h>
#include <math.h>
#include <stdint.h>

#define B_ 8
#define T_ 2048
#define C_ 2048
#define H_ 32
#define HS_ 64
#define M_ (B_*T_)   // 16384

typedef unsigned short ushort_t;

// ---------------- scratch (__device__ globals: allocation-free) ----------------
__device__ float g_tm [(size_t)M_*160];
__device__ float g_xr [(size_t)M_*C_];
__device__ float g_xk [(size_t)M_*C_];
__device__ float g_xv [(size_t)M_*C_];
__device__ float g_xw [(size_t)M_*C_];
__device__ float g_xv2[(size_t)M_*C_];
__device__ float g_r  [(size_t)M_*C_];
__device__ float g_k  [(size_t)M_*C_];
__device__ float g_v  [(size_t)M_*C_];
__device__ float g_v2 [(size_t)M_*C_];
__device__ float g_d  [(size_t)M_*C_];
__device__ float g_lw [(size_t)M_*64];
__device__ float g_lv2[(size_t)M_*64];
__device__ float g_yw [(size_t)M_*C_];

// activation bf16 hi/lo split (reused across the sequential GEMMs)
__device__ ushort_t g_ah[(size_t)M_*C_];
__device__ ushort_t g_al[(size_t)M_*C_];

// transposed + split weights: [N, K] bf16 hi/lo
__device__ ushort_t g_wrh[(size_t)C_*C_];
__device__ ushort_t g_wrl[(size_t)C_*C_];
__device__ ushort_t g_wkh[(size_t)C_*C_];
__device__ ushort_t g_wkl[(size_t)C_*C_];
__device__ ushort_t g_wvh[(size_t)C_*C_];
__device__ ushort_t g_wvl[(size_t)C_*C_];
__device__ ushort_t g_woh[(size_t)C_*C_];
__device__ ushort_t g_wol[(size_t)C_*C_];

// ================= low-level helpers (base-target PTX only) =================
__device__ __forceinline__ uint32_t smem_u32(const void* p) {
    uint32_t a;
    asm("{ .reg .u64 t; cvta.to.shared.u64 t, %1; cvt.u32.u64 %0, t; }" : "=r"(a) : "l"(p));
    return a;
}
__device__ __forceinline__ void cp16(uint32_t dst, const void* src) {
    asm volatile("cp.async.cg.shared.global [%0], [%1], 16;" :: "r"(dst), "l"(src) : "memory");
}
#define CP_COMMIT() asm volatile("cp.async.commit_group;" ::: "memory")
#define CP_WAIT1()  asm volatile("cp.async.wait_group 1;"  ::: "memory")

__device__ __forceinline__ void ldsm_x4(uint32_t* r, uint32_t a) {
    asm volatile("ldmatrix.sync.aligned.m8n8.x4.shared.b16 {%0,%1,%2,%3}, [%4];"
        : "=r"(r[0]), "=r"(r[1]), "=r"(r[2]), "=r"(r[3]) : "r"(a));
}
__device__ __forceinline__ void mma16816(float* c, const uint32_t* a, const uint32_t* b) {
    asm volatile("mma.sync.aligned.m16n8k16.row.col.f32.bf16.bf16.f32 "
        "{%0,%1,%2,%3}, {%4,%5,%6,%7}, {%8,%9}, {%0,%1,%2,%3};"
        : "+f"(c[0]), "+f"(c[1]), "+f"(c[2]), "+f"(c[3])
        : "r"(a[0]), "r"(a[1]), "r"(a[2]), "r"(a[3]), "r"(b[0]), "r"(b[1]));
}

__device__ __forceinline__ void cvt_split4(float4 v, uint2& hi, uint2& lo) {
    __nv_bfloat16 bx = __float2bfloat16(v.x), by = __float2bfloat16(v.y),
                  bz = __float2bfloat16(v.z), bw = __float2bfloat16(v.w);
    hi.x = (uint32_t)__bfloat16_as_ushort(bx) | ((uint32_t)__bfloat16_as_ushort(by) << 16);
    hi.y = (uint32_t)__bfloat16_as_ushort(bz) | ((uint32_t)__bfloat16_as_ushort(bw) << 16);
    __nv_bfloat16 lx = __float2bfloat16(v.x - __bfloat162float(bx));
    __nv_bfloat16 ly = __float2bfloat16(v.y - __bfloat162float(by));
    __nv_bfloat16 lz = __float2bfloat16(v.z - __bfloat162float(bz));
    __nv_bfloat16 lw = __float2bfloat16(v.w - __bfloat162float(bw));
    lo.x = (uint32_t)__bfloat16_as_ushort(lx) | ((uint32_t)__bfloat16_as_ushort(ly) << 16);
    lo.y = (uint32_t)__bfloat16_as_ushort(lz) | ((uint32_t)__bfloat16_as_ushort(lw) << 16);
}

// ---------------- weight transpose + bf16 hi/lo split: T[n][k] = W[k][n] ----------------
__global__ void __launch_bounds__(256) wsplit_t(
    const float* __restrict__ W,
    ushort_t* __restrict__ Th, ushort_t* __restrict__ Tl)
{
    __shared__ float ts[32][33];
    int n0 = blockIdx.x * 32, k0 = blockIdx.y * 32;
    int tx = threadIdx.x & 31, ty = threadIdx.x >> 5;
#pragma unroll
    for (int e = 0; e < 4; e++)
        ts[ty + 8*e][tx] = W[(size_t)(k0 + ty + 8*e)*C_ + n0 + tx];
    __syncthreads();
#pragma unroll
    for (int e = 0; e < 4; e++) {
        int n = ty + 8*e;
        float v = ts[tx][n];
        __nv_bfloat16 h = __float2bfloat16(v);
        Th[(size_t)(n0+n)*C_ + k0 + tx] = __bfloat16_as_ushort(h);
        Tl[(size_t)(n0+n)*C_ + k0 + tx] =
            __bfloat16_as_ushort(__float2bfloat16(v - __bfloat162float(h)));
    }
}

// ---------------- activation fp32 -> bf16 hi/lo split ----------------
__global__ void __launch_bounds__(256) asplit(
    const float* __restrict__ X, ushort_t* __restrict__ Hi, ushort_t* __restrict__ Lo)
{
    size_t i = ((size_t)blockIdx.x*256 + threadIdx.x) * 4;
    float4 v = *(const float4*)(X + i);
    uint2 h, l;
    cvt_split4(v, h, l);
    *(uint2*)(Hi + i) = h;
    *(uint2*)(Lo + i) = l;
}

// ---------------- bf16x3 HMMA GEMM: C[M,N] = A[M,K] @ B[K,N] ----------------
// A hi/lo [M,K] row-major bf16, B = W^T hi/lo [N,K] row-major bf16, C fp32.
// CTA 128x128, 256 threads, warp tile 32x64, K-chunk 32, 3-stage cp.async pipe.
#define LDB     80          // padded row bytes (40 bf16): conflict-free ldmatrix
#define SZ_A    (128*LDB)   // 10240 per buffer
#define STAGE_B (4*SZ_A)    // Ah, Al, Bh, Bl
#define NSTAGE  3
#define GEMM_SMEM (NSTAGE*STAGE_B)   // 122880

__device__ __forceinline__ void gemm_load_stage(
    uint32_t sb, int s, const ushort_t* Ah, const ushort_t* Al,
    const ushort_t* Bh, const ushort_t* Bl, int m0, int n0, int kt, int tid)
{
    int k0 = kt * 32;
    uint32_t base = sb + s*STAGE_B;
#pragma unroll
    for (int e = 0; e < 2; e++) {
        int q = tid + 256*e;          // 0..511
        int row = q >> 2, c = q & 3;
        uint32_t d = base + row*LDB + c*16;
        size_t offA = (size_t)(m0 + row)*C_ + k0 + c*8;
        size_t offB = (size_t)(n0 + row)*C_ + k0 + c*8;
        cp16(d,           Ah + offA);
        cp16(d +   SZ_A,  Al + offA);
        cp16(d + 2*SZ_A,  Bh + offB);
        cp16(d + 3*SZ_A,  Bl + offB);
    }
    CP_COMMIT();
}

__global__ void __launch_bounds__(256, 1) gemm_bf3(
    const ushort_t* __restrict__ Ah, const ushort_t* __restrict__ Al,
    const ushort_t* __restrict__ Bh, const ushort_t* __restrict__ Bl,
    float* __restrict__ Cm)
{
    extern __shared__ char smem[];
    uint32_t sb = smem_u32(smem);
    int tid = threadIdx.x, lane = tid & 31, w = tid >> 5;
    int wm = w & 3, wn = w >> 2;           // 4 x 2 warp grid
    int m0 = blockIdx.y * 128, n0 = blockIdx.x * 128;

    float acc[2][8][4];
#pragma unroll
    for (int i = 0; i < 2; i++)
#pragma unroll
        for (int j = 0; j < 8; j++)
#pragma unroll
            for (int q = 0; q < 4; q++) acc[i][j][q] = 0.f;

    gemm_load_stage(sb, 0, Ah, Al, Bh, Bl, m0, n0, 0, tid);
    gemm_load_stage(sb, 1, Ah, Al, Bh, Bl, m0, n0, 1, tid);

    // precomputed intra-warp ldmatrix offsets
    uint32_t a_off = (uint32_t)((wm*32 + (lane & 15))*LDB + (lane >> 4)*16);
    uint32_t b_off = (uint32_t)((wn*64 + (lane & 7) + ((lane >> 4) & 1)*8)*LDB
                                + ((lane >> 3) & 1)*16);

    for (int kt = 0; kt < C_/32; kt++) {
        int s = kt % NSTAGE;
        CP_WAIT1();
        __syncthreads();
        if (kt + 2 < C_/32)
            gemm_load_stage(sb, (kt+2) % NSTAGE, Ah, Al, Bh, Bl, m0, n0, kt+2, tid);

        uint32_t base = sb + s*STAGE_B;
#pragma unroll
        for (int kk = 0; kk < 2; kk++) {
            uint32_t ah[2][4], al[2][4], bh[4][4], bl[4][4];
#pragma unroll
            for (int mt = 0; mt < 2; mt++) {
                uint32_t addr = base + a_off + mt*16*LDB + kk*32;
                ldsm_x4(ah[mt], addr);
                ldsm_x4(al[mt], addr + SZ_A);
            }
#pragma unroll
            for (int g = 0; g < 4; g++) {
                uint32_t addr = base + 2*SZ_A + b_off + g*16*LDB + kk*32;
                ldsm_x4(bh[g], addr);
                ldsm_x4(bl[g], addr + SZ_A);
            }
#pragma unroll
            for (int mt = 0; mt < 2; mt++)
#pragma unroll
                for (int nt = 0; nt < 8; nt++) {
                    const uint32_t* bph = &bh[nt >> 1][(nt & 1)*2];
                    const uint32_t* bpl = &bl[nt >> 1][(nt & 1)*2];
                    mma16816(acc[mt][nt], ah[mt], bph);   // hh
                    mma16816(acc[mt][nt], ah[mt], bpl);   // h*lo
                    mma16816(acc[mt][nt], al[mt], bph);   // lo*h
                }
        }
    }

    // epilogue: direct fp32 stores
#pragma unroll
    for (int mt = 0; mt < 2; mt++) {
        int r0 = m0 + wm*32 + mt*16 + (lane >> 2);
#pragma unroll
        for (int nt = 0; nt < 8; nt++) {
            int c0 = n0 + wn*64 + nt*8 + (lane & 3)*2;
            *(float2*)&Cm[(size_t)r0*C_ + c0] =
                make_float2(acc[mt][nt][0], acc[mt][nt][1]);
            *(float2*)&Cm[(size_t)(r0+8)*C_ + c0] =
                make_float2(acc[mt][nt][2], acc[mt][nt][3]);
        }
    }
}

// ---------------- skinny GEMM + tanh ----------------
template<int NS, bool FUSE>
__global__ void __launch_bounds__(256) skinny_tanh_gemm(
    const float* __restrict__ A, const float* __restrict__ W,
    float* __restrict__ out,
    const float* __restrict__ shift, const float* __restrict__ maax)
{
    __shared__ float As[32*68];
    __shared__ float Ws[32*NS];
    const int tid = threadIdx.x;
    const int m0  = blockIdx.x * 64;
    const int row = tid >> 2;
    const int cg  = tid & 3;

    float acc[NS/4];
#pragma unroll
    for (int i = 0; i < NS/4; i++) acc[i] = 0.f;

    for (int k0 = 0; k0 < C_; k0 += 32) {
#pragma unroll
        for (int e = 0; e < 2; e++) {
            int q  = tid + 256*e;
            int r  = q >> 3;
            int c4 = (q & 7) * 4;
            int m  = m0 + r;
            float4 val;
            if (FUSE) {
                float4 xv = *(const float4*)(A + (size_t)m*C_ + k0 + c4);
                int t = m & (T_-1);
                int b = m >> 11;
                float4 xp = (t > 0) ? *(const float4*)(A + (size_t)(m-1)*C_ + k0 + c4)
                                    : *(const float4*)(shift + (size_t)b*C_ + k0 + c4);
                float4 mx = *(const float4*)(maax + k0 + c4);
                val.x = xv.x + (xp.x - xv.x)*mx.x;
                val.y = xv.y + (xp.y - xv.y)*mx.y;
                val.z = xv.z + (xp.z - xv.z)*mx.z;
                val.w = xv.w + (xp.w - xv.w)*mx.w;
            } else {
                val = *(const float4*)(A + (size_t)m*C_ + k0 + c4);
            }
            As[(c4+0)*68 + r] = val.x;
            As[(c4+1)*68 + r] = val.y;
            As[(c4+2)*68 + r] = val.z;
            As[(c4+3)*68 + r] = val.w;
        }
        {
            const float4* src = (const float4*)(W + (size_t)k0*NS);
            for (int q = tid; q < 32*NS/4; q += 256)
                ((float4*)Ws)[q] = src[q];
        }
        __syncthreads();
#pragma unroll 8
        for (int k = 0; k < 32; k++) {
            float a = As[k*68 + row];
            const float* wrow = Ws + k*NS + cg*(NS/4);
#pragma unroll
            for (int j = 0; j < NS/16; j++) {
                float4 w4 = *(const float4*)(wrow + j*4);
                acc[j*4+0] = fmaf(a, w4.x, acc[j*4+0]);
                acc[j*4+1] = fmaf(a, w4.y, acc[j*4+1]);
                acc[j*4+2] = fmaf(a, w4.z, acc[j*4+2]);
                acc[j*4+3] = fmaf(a, w4.w, acc[j*4+3]);
            }
        }
        __syncthreads();
    }
    float* orow = out + (size_t)(m0+row)*NS + cg*(NS/4);
#pragma unroll
    for (int i = 0; i < NS/4; i++) orow[i] = tanhf(acc[i]);
}

// ---------------- 5-way mix apply ----------------
__global__ void __launch_bounds__(256) mix_apply_f(
    const float* __restrict__ x, const float* __restrict__ shift,
    const float* __restrict__ tm, const float* __restrict__ w2,
    const float* __restrict__ maa, float* __restrict__ out, int f)
{
    __shared__ float tmf[32*32];
    __shared__ float w2f[32*64];
    int tid = threadIdx.x;
    int m0 = blockIdx.y * 32;
    int c0 = blockIdx.x * 64;
    {
        int r = tid >> 3, c4 = (tid & 7) * 4;
        *(float4*)&tmf[r*32 + c4] =
            *(const float4*)(tm + (size_t)(m0+r)*160 + f*32 + c4);
    }
#pragma unroll
    for (int e = 0; e < 2; e++) {
        int q = tid + 256*e;
        int d = q >> 4, c4 = (q & 15) * 4;
        *(float4*)&w2f[d*64 + c4] =
            *(const float4*)(w2 + (size_t)(f*32+d)*C_ + c0 + c4);
    }
    __syncthreads();
#pragma unroll
    for (int e = 0; e < 2; e++) {
        int p = tid + 256*e;
        int r  = p >> 4;
        int c4 = (p & 15) * 4;
        int m = m0 + r;
        int c = c0 + c4;
        float4 acc = make_float4(0.f,0.f,0.f,0.f);
#pragma unroll
        for (int d = 0; d < 32; d++) {
            float tv = tmf[r*32 + d];
            float4 w4 = *(const float4*)&w2f[d*64 + c4];
            acc.x = fmaf(tv, w4.x, acc.x);
            acc.y = fmaf(tv, w4.y, acc.y);
            acc.z = fmaf(tv, w4.z, acc.z);
            acc.w = fmaf(tv, w4.w, acc.w);
        }
        float4 xv = *(const float4*)(x + (size_t)m*C_ + c);
        int t = m & (T_-1), b = m >> 11;
        float4 xp = (t > 0) ? *(const float4*)(x + (size_t)(m-1)*C_ + c)
                            : *(const float4*)(shift + (size_t)b*C_ + c);
        float4 ma = *(const float4*)(maa + c);
        float4 o;
        o.x = xv.x + (xp.x - xv.x)*(ma.x + acc.x);
        o.y = xv.y + (xp.y - xv.y)*(ma.y + acc.y);
        o.z = xv.z + (xp.z - xv.z)*(ma.z + acc.z);
        o.w = xv.w + (xp.w - xv.w)*(ma.w + acc.w);
        *(float4*)(out + (size_t)m*C_ + c) = o;
    }
}

// ---------------- small-K GEMM (K=64) with fused epilogues ----------------
template<int MODE>
__global__ void __launch_bounds__(256) smallk_gemm(
    const float* __restrict__ A, const float* __restrict__ W,
    const float* __restrict__ td, float* __restrict__ out1,
    float* __restrict__ karr)
{
    __shared__ float As[32*64];
    __shared__ float Ws[64*128];
    int tid = threadIdx.x;
    int m0 = blockIdx.y * 32, c0 = blockIdx.x * 128;
    {
        const float4* src = (const float4*)(A + (size_t)m0*64);
#pragma unroll
        for (int q = tid; q < 512; q += 256) ((float4*)As)[q] = src[q];
    }
#pragma unroll
    for (int e = 0; e < 8; e++) {
        int q = tid + 256*e;
        int kr = q >> 5, c4 = (q & 31) * 4;
        *(float4*)&Ws[kr*128 + c4] = *(const float4*)(W + (size_t)kr*C_ + c0 + c4);
    }
    __syncthreads();
    int ty = tid >> 4, tx = tid & 15;
    int r0 = ty * 2;
    float acc[2][8];
#pragma unroll
    for (int i = 0; i < 2; i++)
#pragma unroll
        for (int j = 0; j < 8; j++) acc[i][j] = 0.f;
#pragma unroll
    for (int k = 0; k < 64; k++) {
        float a0 = As[r0*64 + k];
        float a1 = As[(r0+1)*64 + k];
        float4 b0 = *(const float4*)&Ws[k*128 + tx*8];
        float4 b1 = *(const float4*)&Ws[k*128 + tx*8 + 4];
        float bv[8] = {b0.x,b0.y,b0.z,b0.w,b1.x,b1.y,b1.z,b1.w};
#pragma unroll
        for (int j = 0; j < 8; j++) {
            acc[0][j] = fmaf(a0, bv[j], acc[0][j]);
            acc[1][j] = fmaf(a1, bv[j], acc[1][j]);
        }
    }
#pragma unroll
    for (int rr = 0; rr < 2; rr++) {
        int m = m0 + r0 + rr;
        size_t base = (size_t)m*C_ + c0 + tx*8;
        if (MODE == 0) {
#pragma unroll
            for (int j = 0; j < 8; j++) {
                float w = td[c0 + tx*8 + j] + acc[rr][j];
                float dd = expf(-expf(w));
                out1[base + j] = dd;
                karr[base + j] *= (1.0f - dd);
            }
        } else {
#pragma unroll
            for (int j = 0; j < 8; j++) out1[base + j] += acc[rr][j];
        }
    }
}

// ---------------- WKV scan ----------------
__global__ void __launch_bounds__(64) wkv_scan(
    const float* __restrict__ rp, const float* __restrict__ kp,
    const float* __restrict__ vp, const float* __restrict__ dp,
    const float* __restrict__ S0, float* __restrict__ yp,
    float* __restrict__ Sout)
{
    int bh = blockIdx.x;
    int j = threadIdx.x;
    int b = bh >> 5, h = bh & (H_-1);
    float S[64];
    const float* s0 = S0 + (size_t)bh*HS_*HS_ + j;
#pragma unroll
    for (int i = 0; i < 64; i++) S[i] = s0[(size_t)i*64];
    __shared__ float4 skd[64];
    size_t idx = (size_t)b*T_*C_ + (size_t)h*64 + j;
    float rr = rp[idx], kk = kp[idx], dd = dp[idx], vv = vp[idx];
    for (int t = 0; t < T_; t++) {
        float rn = 0.f, kn = 0.f, dn = 0.f, vn = 0.f;
        if (t + 1 < T_) {
            size_t nx = idx + C_;
            rn = rp[nx]; kn = kp[nx]; dn = dp[nx]; vn = vp[nx];
        }
        skd[j] = make_float4(rr, kk, dd, 0.f);
        __syncthreads();
        float acc = 0.f;
#pragma unroll
        for (int i = 0; i < 64; i++) {
            float4 q = skd[i];
            acc  = fmaf(q.x, S[i], acc);
            S[i] = fmaf(q.z, S[i], q.y * vv);
        }
        yp[idx] = acc;
        __syncthreads();
        idx += C_;
        rr = rn; kk = kn; dd = dn; vv = vn;
    }
    float* so = Sout + (size_t)bh*HS_*HS_ + j;
#pragma unroll
    for (int i = 0; i < 64; i++) so[(size_t)i*64] = S[i];
}

// ---------------- fused add + LayerNorm, emits bf16 hi/lo split ----------------
__global__ void __launch_bounds__(256) ln_add_split(
    const float* __restrict__ a, const float* __restrict__ b,
    const float* __restrict__ lw, const float* __restrict__ lb,
    ushort_t* __restrict__ oh, ushort_t* __restrict__ ol)
{
    int m = blockIdx.x;
    int tid = threadIdx.x;
    const float* ar = a + (size_t)m*C_;
    const float* br = b + (size_t)m*C_;
    float vals[8];
    float s = 0.f, s2 = 0.f;
#pragma unroll
    for (int i = 0; i < 8; i++) {
        int c = tid + 256*i;
        float u = ar[c] + br[c];
        vals[i] = u; s += u; s2 = fmaf(u, u, s2);
    }
#pragma unroll
    for (int o = 16; o > 0; o >>= 1) {
        s  += __shfl_xor_sync(0xffffffffu, s,  o);
        s2 += __shfl_xor_sync(0xffffffffu, s2, o);
    }
    __shared__ float sa[8], sb2[8];
    if ((tid & 31) == 0) { sa[tid>>5] = s; sb2[tid>>5] = s2; }
    __syncthreads();
    s = 0.f; s2 = 0.f;
#pragma unroll
    for (int i = 0; i < 8; i++) { s += sa[i]; s2 += sb2[i]; }
    float mu  = s * (1.0f/C_);
    float var = s2 * (1.0f/C_) - mu*mu;
    float inv = rsqrtf(var + 1e-5f);
#pragma unroll
    for (int i = 0; i < 8; i++) {
        int c = tid + 256*i;
        float v = (vals[i] - mu)*inv*lw[c] + lb[c];
        __nv_bfloat16 hb = __float2bfloat16(v);
        oh[(size_t)m*C_ + c] = __bfloat16_as_ushort(hb);
        ol[(size_t)m*C_ + c] =
            __bfloat16_as_ushort(__float2bfloat16(v - __bfloat162float(hb)));
    }
}

__global__ void copy_xlast(const float* __restrict__ x, float* __restrict__ o)
{
    int i = blockIdx.x*256 + threadIdx.x;
    int b = i >> 11, c = i & (C_-1);
    o[i] = x[((size_t)b*T_ + (T_-1))*C_ + c];
}

// ---------------- launcher ----------------
extern "C" void kernel_launch(void* const* d_in, const int* in_sizes, int n_in,
                              void* d_out, int out_size)
{
    (void)in_sizes; (void)n_in;
    const float* x     = (const float*)d_in[0];
    const float* shift = (const float*)d_in[1];
    const float* wkv0  = (const float*)d_in[2];
    const float* maax  = (const float*)d_in[3];
    const float* maar  = (const float*)d_in[4];
    const float* maak  = (const float*)d_in[5];
    const float* maav  = (const float*)d_in[6];
    const float* maaw  = (const float*)d_in[7];
    const float* maav2 = (const float*)d_in[8];
    const float* w1    = (const float*)d_in[9];
    const float* w2    = (const float*)d_in[10];
    const float* tdec  = (const float*)d_in[11];
    const float* dw1   = (const float*)d_in[12];
    const float* dw2   = (const float*)d_in[13];
    const float* vw1   = (const float*)d_in[14];
    const float* vw2   = (const float*)d_in[15];
    const float* Wr    = (const float*)d_in[17];
    const float* Wk    = (const float*)d_in[18];
    const float* Wv    = (const float*)d_in[19];
    const float* Wo    = (const float*)d_in[20];
    const float* lnw   = (const float*)d_in[21];
    const float* lnb   = (const float*)d_in[22];
    float* out = (float*)d_out;

    float *tm,*xr,*xk,*xv,*xw,*xv2,*rb,*kb,*vb,*v2b,*db,*lwv,*lv2,*yw;
    ushort_t *ah,*al,*wrh,*wrl,*wkh,*wkl,*wvh,*wvl,*woh,*wol;
    cudaGetSymbolAddress((void**)&tm,  g_tm);
    cudaGetSymbolAddress((void**)&xr,  g_xr);
    cudaGetSymbolAddress((void**)&xk,  g_xk);
    cudaGetSymbolAddress((void**)&xv,  g_xv);
    cudaGetSymbolAddress((void**)&xw,  g_xw);
    cudaGetSymbolAddress((void**)&xv2, g_xv2);
    cudaGetSymbolAddress((void**)&rb,  g_r);
    cudaGetSymbolAddress((void**)&kb,  g_k);
    cudaGetSymbolAddress((void**)&vb,  g_v);
    cudaGetSymbolAddress((void**)&v2b, g_v2);
    cudaGetSymbolAddress((void**)&db,  g_d);
    cudaGetSymbolAddress((void**)&lwv, g_lw);
    cudaGetSymbolAddress((void**)&lv2, g_lv2);
    cudaGetSymbolAddress((void**)&yw,  g_yw);
    cudaGetSymbolAddress((void**)&ah,  g_ah);
    cudaGetSymbolAddress((void**)&al,  g_al);
    cudaGetSymbolAddress((void**)&wrh, g_wrh);
    cudaGetSymbolAddress((void**)&wrl, g_wrl);
    cudaGetSymbolAddress((void**)&wkh, g_wkh);
    cudaGetSymbolAddress((void**)&wkl, g_wkl);
    cudaGetSymbolAddress((void**)&wvh, g_wvh);
    cudaGetSymbolAddress((void**)&wvl, g_wvl);
    cudaGetSymbolAddress((void**)&woh, g_woh);
    cudaGetSymbolAddress((void**)&wol, g_wol);

    cudaFuncSetAttribute(gemm_bf3, cudaFuncAttributeMaxDynamicSharedMemorySize, GEMM_SMEM);

    // 0) weight transpose + bf16 split
    {
        dim3 gt(C_/32, C_/32);
        wsplit_t<<<gt,256>>>(Wr, wrh, wrl);
        wsplit_t<<<gt,256>>>(Wk, wkh, wkl);
        wsplit_t<<<gt,256>>>(Wv, wvh, wvl);
        wsplit_t<<<gt,256>>>(Wo, woh, wol);
    }

    // 1) LoRA-5 projection with fused token-shift mixing
    skinny_tanh_gemm<160, true><<<M_/64, 256>>>(x, w1, tm, shift, maax);

    // 2) 5-way mix
    {
        dim3 g(C_/64, M_/32);
        mix_apply_f<<<g,256>>>(x, shift, tm, w2, maar,  xr,  0);
        mix_apply_f<<<g,256>>>(x, shift, tm, w2, maak,  xk,  1);
        mix_apply_f<<<g,256>>>(x, shift, tm, w2, maav,  xv,  2);
        mix_apply_f<<<g,256>>>(x, shift, tm, w2, maaw,  xw,  3);
        mix_apply_f<<<g,256>>>(x, shift, tm, w2, maav2, xv2, 4);
    }

    // 3) big projections via HMMA bf16x3 (split activation, then GEMM)
    const int NSPLIT = (int)(((size_t)M_*C_/4) / 256);
    dim3 gg(C_/128, M_/128);
    asplit<<<NSPLIT,256>>>(xr, ah, al);
    gemm_bf3<<<gg,256,GEMM_SMEM>>>(ah, al, wrh, wrl, rb);
    asplit<<<NSPLIT,256>>>(xk, ah, al);
    gemm_bf3<<<gg,256,GEMM_SMEM>>>(ah, al, wkh, wkl, kb);
    asplit<<<NSPLIT,256>>>(xv, ah, al);
    gemm_bf3<<<gg,256,GEMM_SMEM>>>(ah, al, wvh, wvl, vb);
    asplit<<<NSPLIT,256>>>(xv2, ah, al);
    gemm_bf3<<<gg,256,GEMM_SMEM>>>(ah, al, wvh, wvl, v2b);

    // 4) decay / value2 LoRAs
    skinny_tanh_gemm<64, false><<<M_/64, 256>>>(xw,  dw1, lwv, nullptr, nullptr);
    skinny_tanh_gemm<64, false><<<M_/64, 256>>>(xv2, vw1, lv2, nullptr, nullptr);
    {
        dim3 gs(C_/128, M_/32);
        smallk_gemm<0><<<gs,256>>>(lwv, dw2, tdec, db,  kb);
        smallk_gemm<1><<<gs,256>>>(lv2, vw2, nullptr, v2b, nullptr);
    }

    // 5) WKV scan, 6) add v2 + LayerNorm (split output), 7) output projection
    const size_t OFFS = (size_t)M_*C_;
    const size_t OFFX = OFFS + (size_t)B_*H_*HS_*HS_;
    bool full = (size_t)out_size >= OFFX + (size_t)B_*C_;
    float* Sout = full ? (out + OFFS) : tm;
    wkv_scan<<<B_*H_, 64>>>(rb, kb, vb, db, wkv0, yw, Sout);
    ln_add_split<<<M_, 256>>>(yw, v2b, lnw, lnb, ah, al);
    gemm_bf3<<<gg,256,GEMM_SMEM>>>(ah, al, woh, wol, out);
    if (full) copy_xlast<<<(B_*C_)/256, 256>>>(x, out + OFFX);
}